// round 16
// baseline (speedup 1.0000x reference)
#include <cuda_runtime.h>
#include <cstdint>

// RationalsModel: out[i] = P(x[i]) / (|x[i] * Q(x[i])| + 1)
//   P = sum_{p=0}^{63} coef[p]      * x^p
//   Q = sum_{p=0}^{63} coef[64 + p] * x^p
//
// R16: every variant sits at the FFMA2 port floor (fma% = 66.7% port +
// ~3% epilogue everywhere). The 1.2us gap between smem kernels (21.5-21.7)
// and R12's no-smem LDC kernel (20.35) is per-block prologue cost (coef
// LDG + syncthreads x 4096 blocks) + wave-2 ramp. Fix: grid-stride blocks.
// grid=1024 (single wave at regs~44), each block runs 4 tiles; prologue
// paid once per block, coef stays in smem across tiles. Inner loop = R14's
// best: 8 (N,D) lanes, 1 LDS.64 broadcast + 8 FFMA2 per step.

__device__ __forceinline__ uint64_t pack2(float lo, float hi) {
    uint64_t r;
    asm("mov.b64 %0, {%1, %2};" : "=l"(r) : "f"(lo), "f"(hi));
    return r;
}

__device__ __forceinline__ void unpack2(uint64_t v, float& lo, float& hi) {
    asm("mov.b64 {%0, %1}, %2;" : "=f"(lo), "=f"(hi) : "l"(v));
}

// d = a * b + c  (packed 2x f32)
__device__ __forceinline__ uint64_t fma2(uint64_t a, uint64_t b, uint64_t c) {
    uint64_t d;
    asm("fma.rn.f32x2 %0, %1, %2, %3;" : "=l"(d) : "l"(a), "l"(b), "l"(c));
    return d;
}

static constexpr int THREADS = 128;
static constexpr int LANES = 8;                                     // (N,D) lanes
static constexpr int ELEMS_PER_TILE = THREADS * LANES;              // 1024
static constexpr int F4_PER_TILE = ELEMS_PER_TILE / 4;              // 256
static constexpr int GRID = 1024;                                   // single wave

__global__ __launch_bounds__(THREADS)
void rational_kernel(const float4* __restrict__ x4,
                     const float* __restrict__ coef,
                     float4* __restrict__ out4,
                     int num_tiles)
{
    // sP[p] = (lo: coef[p], hi: coef[64+p]) — one LDS.64 broadcast per step.
    __shared__ uint64_t sP[64];

    int tid = threadIdx.x;
    if (tid < 64) {
        uint32_t lo = __float_as_uint(coef[tid]);
        uint32_t hi = __float_as_uint(coef[64 + tid]);
        sP[tid] = (uint64_t)lo | ((uint64_t)hi << 32);
    }
    __syncthreads();

    // Grid-stride over tiles: prologue amortized across all tiles of a block.
#pragma unroll 1
    for (int tile = blockIdx.x; tile < num_tiles; tile += GRID) {
        int base = tile * F4_PER_TILE + tid;
        float4 a = x4[base];
        float4 b = x4[base + THREADS];

        float xs[8] = {a.x, a.y, a.z, a.w, b.x, b.y, b.z, b.w};

        // x2[i] = dup2(x_i): multiplier for the (N,D) packed Horner lane.
        uint64_t x2[LANES];
#pragma unroll
        for (int j = 0; j < LANES; j++) x2[j] = pack2(xs[j], xs[j]);

        // acc[i] = (P_horner_i, Q_horner_i)
        uint64_t acc[LANES];
        {
            uint64_t c63 = sP[63];
#pragma unroll
            for (int j = 0; j < LANES; j++) acc[j] = c63;
        }

        // Dual Horner, fully unrolled: per step ONE LDS.64 broadcast (cn,cm)
        // feeding 8 FFMA2 (24 fma-pipe cycles).
#pragma unroll
        for (int p = 62; p >= 0; p--) {
            uint64_t cp = sP[p];
#pragma unroll
            for (int j = 0; j < LANES; j++) {
                acc[j] = fma2(acc[j], x2[j], cp);
            }
        }

        // Epilogue: den = x * Q(x); out = P / (|den| + 1).
        float4 o[2];
        float* of = reinterpret_cast<float*>(o);
#pragma unroll
        for (int j = 0; j < LANES; j++) {
            float pn, qd;
            unpack2(acc[j], pn, qd);
            of[j] = __fdividef(pn, fabsf(xs[j] * qd) + 1.0f);
        }

        out4[base] = o[0];
        out4[base + THREADS] = o[1];
    }
}

extern "C" void kernel_launch(void* const* d_in, const int* in_sizes, int n_in,
                              void* d_out, int out_size) {
    const float* x    = (const float*)d_in[0];
    const float* coef = (const float*)d_in[1];
    float* out        = (float*)d_out;

    int N = in_sizes[0];                     // 4194304
    int num_tiles = N / ELEMS_PER_TILE;      // 4096

    rational_kernel<<<GRID, THREADS>>>(
        (const float4*)x, coef, (float4*)out, num_tiles);
}

// round 17
// speedup vs baseline: 1.1853x; 1.1853x over previous
#include <cuda_runtime.h>
#include <cstdint>

// RationalsModel: out[i] = P(x[i]) / (|x[i] * Q(x[i])| + 1)
//   P = sum_{p=0}^{63} coef[p]      * x^p
//   Q = sum_{p=0}^{63} coef[64 + p] * x^p
//
// R17: even-odd Horner split. P(x) = E(x^2) + x*O(x^2); packed lane
// acc=(E,O), multiplier dup2(x^2), coefficient operand = (c_{2k}, c_{2k+1})
// = an ALIGNED u64 in the RAW coefficient array -> one LDC.64, no
// interleave staging. Staging = single plain 512B cudaMemcpyToSymbolAsync
// (~1.2us node, vs R12's 4.2us memcpy2D pair). Inner loop: 31 steps x
// (2 LDC.64 + 16 FFMA2) at the validated FFMA2 rt=3 port floor, no smem
// (keeps the 2.06GHz DVFS regime).

__device__ __forceinline__ uint64_t pack2(float lo, float hi) {
    uint64_t r;
    asm("mov.b64 %0, {%1, %2};" : "=l"(r) : "f"(lo), "f"(hi));
    return r;
}

__device__ __forceinline__ void unpack2(uint64_t v, float& lo, float& hi) {
    asm("mov.b64 {%0, %1}, %2;" : "=f"(lo), "=f"(hi) : "l"(v));
}

// d = a * b + c  (packed 2x f32)
__device__ __forceinline__ uint64_t fma2(uint64_t a, uint64_t b, uint64_t c) {
    uint64_t d;
    asm("fma.rn.f32x2 %0, %1, %2, %3;" : "=l"(d) : "l"(a), "l"(b), "l"(c));
    return d;
}

// Raw copy: cC[p] = coef[p]. u64 view: pair k = (coef[2k], coef[2k+1]).
// Numerator pairs: k = 0..31. Denominator pairs: k = 32..63.
__constant__ __align__(8) float cC[128];

static constexpr int THREADS = 128;
static constexpr int LANES = 8;                                     // 8 elements
static constexpr int ELEMS_PER_BLOCK = THREADS * LANES;             // 1024
static constexpr int F4_PER_BLOCK = ELEMS_PER_BLOCK / 4;            // 256

__global__ __launch_bounds__(THREADS)
void rational_kernel(const float4* __restrict__ x4,
                     float4* __restrict__ out4)
{
    int tid = threadIdx.x;
    const uint64_t* cp64 = reinterpret_cast<const uint64_t*>(cC);

    int base = blockIdx.x * F4_PER_BLOCK + tid;
    float4 a = x4[base];
    float4 b = x4[base + THREADS];

    float xs[LANES] = {a.x, a.y, a.z, a.w, b.x, b.y, b.z, b.w};

    // t2[i] = dup2(x_i^2): multiplier for the (E,O) packed Horner lane.
    uint64_t t2[LANES];
#pragma unroll
    for (int j = 0; j < LANES; j++) {
        float t = xs[j] * xs[j];
        t2[j] = pack2(t, t);
    }

    // accP = (E_num, O_num), accD = (E_den, O_den)
    uint64_t accP[LANES], accD[LANES];
    {
        uint64_t cn31 = cp64[31];   // (coef[62], coef[63])
        uint64_t cd31 = cp64[63];   // (coef[126], coef[127])
#pragma unroll
        for (int j = 0; j < LANES; j++) { accP[j] = cn31; accD[j] = cd31; }
    }

    // Packed even-odd Horner in t = x^2: 31 steps x (2 LDC.64 + 16 FFMA2).
#pragma unroll
    for (int k = 30; k >= 0; k--) {
        uint64_t cn = cp64[k];        // (coef[2k],    coef[2k+1])
        uint64_t cd = cp64[32 + k];   // (coef[64+2k], coef[64+2k+1])
#pragma unroll
        for (int j = 0; j < LANES; j++) {
            accP[j] = fma2(accP[j], t2[j], cn);
            accD[j] = fma2(accD[j], t2[j], cd);
        }
    }

    // Epilogue: P = E + x*O; Q = Eq + x*Oq; out = P / (|x*Q| + 1).
    float4 o[2];
    float* of = reinterpret_cast<float*>(o);
#pragma unroll
    for (int j = 0; j < LANES; j++) {
        float En, On, Ed, Od;
        unpack2(accP[j], En, On);
        unpack2(accD[j], Ed, Od);
        float x = xs[j];
        float P = fmaf(x, On, En);
        float Q = fmaf(x, Od, Ed);
        of[j] = __fdividef(P, fabsf(x * Q) + 1.0f);
    }

    out4[base] = o[0];
    out4[base + THREADS] = o[1];
}

extern "C" void kernel_launch(void* const* d_in, const int* in_sizes, int n_in,
                              void* d_out, int out_size) {
    const float* x    = (const float*)d_in[0];
    const float* coef = (const float*)d_in[1];
    float* out        = (float*)d_out;

    int N = in_sizes[0];                 // 4194304, divisible by 1024
    int blocks = N / ELEMS_PER_BLOCK;    // 4096

    // Single staging node: raw coefficients -> constant memory (D2D, 512B).
    cudaMemcpyToSymbolAsync(cC, coef, 128 * sizeof(float), 0,
                            cudaMemcpyDeviceToDevice, 0);

    rational_kernel<<<blocks, THREADS>>>(
        (const float4*)x, (float4*)out);
}